// round 13
// baseline (speedup 1.0000x reference)
#include <cuda_runtime.h>
#include <cuda_fp16.h>

// ---------------- problem constants ----------------
#define TOK      32
#define KDIM     4096
#define NDIM     11008
#define NTILE    128                 // output columns per CTA (16 per warp)
#define GRID_N   (NDIM / NTILE)      // 86
#define SPLITK   8
#define NCHUNK_G 64                  // total k-chunks of 64 (== group size)
#define CPC      (NCHUNK_G / SPLITK) // 8 chunks per CTA
#define KWORDS   2048                // int32 words per packed row
#define XROW     520                 // smem A row stride in halfs (1040B, cf-free)

__device__ float g_partial[SPLITK][TOK * NDIM];

// ---------------- helpers ----------------
static __device__ __forceinline__ unsigned smem_u32(const void* p) {
    unsigned a;
    asm("{ .reg .u64 t; cvta.to.shared.u64 t, %1; cvt.u32.u64 %0, t; }"
        : "=r"(a) : "l"(p));
    return a;
}
static __device__ __forceinline__ void ldmatrix_x4(unsigned& a0, unsigned& a1,
                                                   unsigned& a2, unsigned& a3,
                                                   unsigned addr) {
    asm volatile("ldmatrix.sync.aligned.m8n8.x4.shared.b16 {%0,%1,%2,%3}, [%4];"
                 : "=r"(a0), "=r"(a1), "=r"(a2), "=r"(a3) : "r"(addr));
}
static __device__ __forceinline__ void mma16816(float& d0, float& d1, float& d2, float& d3,
                                                unsigned a0, unsigned a1, unsigned a2, unsigned a3,
                                                unsigned b0, unsigned b1) {
    asm volatile("mma.sync.aligned.m16n8k16.row.col.f32.f16.f16.f32 "
                 "{%0,%1,%2,%3}, {%4,%5,%6,%7}, {%8,%9}, {%0,%1,%2,%3};"
                 : "+f"(d0), "+f"(d1), "+f"(d2), "+f"(d3)
                 : "r"(a0), "r"(a1), "r"(a2), "r"(a3), "r"(b0), "r"(b1));
}
static __device__ __forceinline__ unsigned prmt(unsigned a, unsigned b, unsigned s) {
    unsigned r;
    asm("prmt.b32 %0, %1, %2, %3;" : "=r"(r) : "r"(a), "r"(b), "r"(s));
    return r;
}
// (a & b) | c  -> immLut 0xEA ; yields fp16 {64+q} when b=0x00F000F0, c=0x54005400
static __device__ __forceinline__ unsigned lop3_ea(unsigned a, unsigned b, unsigned c) {
    unsigned r;
    asm("lop3.b32 %0, %1, %2, %3, 0xEA;" : "=r"(r) : "r"(a), "r"(b), "r"(c));
    return r;
}
// pack: result = {lo, hi} fp16x2 from two fp32 (first src -> HIGH half)
static __device__ __forceinline__ unsigned f16x2(float hi, float lo) {
    unsigned r;
    asm("cvt.rn.f16x2.f32 %0, %1, %2;" : "=r"(r) : "f"(hi), "f"(lo));
    return r;
}
#define NIB_MASK 0x00F000F0u
#define MAGIC64  0x54005400u

// ---------------- main kernel (prep fused in) ----------------
__global__ void __launch_bounds__(256, 2)
awq_main_kernel(const float* __restrict__ x,
                const int* __restrict__ qweight,
                const float* __restrict__ wscales,
                const float* __restrict__ wzeros,
                const float* __restrict__ bias) {
    __shared__ __align__(16) __half sA[32 * XROW];   // 33280 B
    __shared__ float sX[32 * 9];                      // 1152 B
    __shared__ float sS[CPC * NTILE];                 // 4096 B
    __shared__ float sZ[CPC * NTILE];                 // 4096 B

    const int tid  = threadIdx.x;
    const int wid  = tid >> 5;
    const int lane = tid & 31;
    const int n0   = blockIdx.x * NTILE;
    const int kb   = blockIdx.y;
    const int g0   = kb * CPC;

    // ---- B-side: warp owns 16 n = 2 groups of 8 ----
    const int npbase = (n0 >> 2) + wid * 4 + (lane >> 4);
    const int* qb0 = qweight + (size_t)npbase * KWORDS + g0 * 32 + 8 * (lane & 3);
    const int* qb1 = qb0 + 2 * KWORDS;

    // byte-gather selector: result byte0 = a.byte(bi), byte2 = b.byte(bi)
    const unsigned bi  = (unsigned)((lane >> 2) & 3);
    const unsigned sel = bi | ((4u + bi) << 8);

    // ---- accumulator-side n (per group) ----
    const int nloc0 = wid * 16 + 2 * (lane & 3);
    const int nloc1 = nloc0 + 8;

    // ---- q prefetch ring, depth 2, 2 groups (issue FIRST for latency) ----
    int4 qr[2][2][2];
#pragma unroll
    for (int j = 0; j < 2; ++j) {
        qr[j][0][0] = *reinterpret_cast<const int4*>(qb0 + j * 32);
        qr[j][0][1] = *reinterpret_cast<const int4*>(qb0 + j * 32 + 4);
        qr[j][1][0] = *reinterpret_cast<const int4*>(qb1 + j * 32);
        qr[j][1][1] = *reinterpret_cast<const int4*>(qb1 + j * 32 + 4);
    }

    // ---- s/z prologue: coalesced into smem ----
    {
        const int g = tid >> 5, nn = lane * 4;
        *reinterpret_cast<float4*>(&sS[g * NTILE + nn]) =
            *reinterpret_cast<const float4*>(wscales + (size_t)(g0 + g) * NDIM + n0 + nn);
        *reinterpret_cast<float4*>(&sZ[g * NTILE + nn]) =
            *reinterpret_cast<const float4*>(wzeros + (size_t)(g0 + g) * NDIM + n0 + nn);
    }

    // ---- fused A prep: thread owns (token row r, local group gl) ----
    // khat(j,par) = 16*((j>>1)&3) + 2*(j>>3) + (j&1) + 8*par, k = 2j+par
    // inverted: dest uint4 d, half-slot s  <-  k = 16*(s>>1)+4*(d>>1)+2*(s&1)+(d&1)
    {
        const int r  = tid >> 3;        // 0..31 token row
        const int gl = tid & 7;         // 0..7 local group (== chunk i)
        const float4* xs = reinterpret_cast<const float4*>(
            x + (size_t)r * KDIM + g0 * 64 + gl * 64);
        unsigned pk[8][4];
#pragma unroll
        for (int u = 0; u < 16; ++u) {
            float4 v = xs[u];
            // float4 u covers k = 4u+{0,1,2,3}
            pk[2 * (u & 3)    ][u >> 2] = f16x2(v.z, v.x);   // d even: lo=k+0, hi=k+2
            pk[2 * (u & 3) + 1][u >> 2] = f16x2(v.w, v.y);   // d odd : lo=k+1, hi=k+3
        }
        // group sum of the ROUNDED values (fp32, fixed order)
        float psum = 0.f;
#pragma unroll
        for (int d = 0; d < 8; ++d)
#pragma unroll
            for (int s2 = 0; s2 < 4; ++s2) {
                float2 fv = __half22float2(*reinterpret_cast<__half2*>(&pk[d][s2]));
                psum += fv.x;
                psum += fv.y;
            }
        uint4* dstA = reinterpret_cast<uint4*>(sA + r * XROW + gl * 64);
#pragma unroll
        for (int d = 0; d < 8; ++d)
            dstA[d] = make_uint4(pk[d][0], pk[d][1], pk[d][2], pk[d][3]);
        sX[r * 9 + gl] = psum;
    }
    __syncthreads();   // the only barrier

    // fin[mt][ng][4]
    float fin[2][2][4];
#pragma unroll
    for (int m = 0; m < 2; ++m)
#pragma unroll
        for (int g = 0; g < 2; ++g)
#pragma unroll
            for (int c = 0; c < 4; ++c) fin[m][g][c] = 0.f;

    const unsigned Abase = smem_u32(sA)
        + (unsigned)(((lane & 15) * XROW + (lane >> 4) * 8) * 2);

#pragma unroll
    for (int i = 0; i < CPC; ++i) {
        const int slot = i & 1;
        const int4 qg0a = qr[slot][0][0], qg0b = qr[slot][0][1];
        const int4 qg1a = qr[slot][1][0], qg1b = qr[slot][1][1];
        if (i + 2 < CPC) {
            qr[slot][0][0] = *reinterpret_cast<const int4*>(qb0 + (i + 2) * 32);
            qr[slot][0][1] = *reinterpret_cast<const int4*>(qb0 + (i + 2) * 32 + 4);
            qr[slot][1][0] = *reinterpret_cast<const int4*>(qb1 + (i + 2) * 32);
            qr[slot][1][1] = *reinterpret_cast<const int4*>(qb1 + (i + 2) * 32 + 4);
        }

        float acc[2][2][4];
#pragma unroll
        for (int m = 0; m < 2; ++m)
#pragma unroll
            for (int g = 0; g < 2; ++g)
#pragma unroll
                for (int c = 0; c < 4; ++c) acc[m][g][c] = 0.f;

        const int qa0[8] = { qg0a.x, qg0a.y, qg0a.z, qg0a.w,
                             qg0b.x, qg0b.y, qg0b.z, qg0b.w };
        const int qa1[8] = { qg1a.x, qg1a.y, qg1a.z, qg1a.w,
                             qg1b.x, qg1b.y, qg1b.z, qg1b.w };
#pragma unroll
        for (int s4 = 0; s4 < 4; ++s4) {
            // PRMT gathers this thread's n-byte from both k-words;
            // LOP3 injects nibbles into fp16 {64+q} (hi nibble at mantissa[7:4])
            const unsigned p0  = prmt((unsigned)qa0[2 * s4], (unsigned)qa0[2 * s4 + 1], sel);
            const unsigned b01 = lop3_ea(p0,      NIB_MASK, MAGIC64);   // odd k  -> b1
            const unsigned b00 = lop3_ea(p0 << 4, NIB_MASK, MAGIC64);   // even k -> b0
            const unsigned p1  = prmt((unsigned)qa1[2 * s4], (unsigned)qa1[2 * s4 + 1], sel);
            const unsigned b11 = lop3_ea(p1,      NIB_MASK, MAGIC64);
            const unsigned b10 = lop3_ea(p1 << 4, NIB_MASK, MAGIC64);
#pragma unroll
            for (int mt = 0; mt < 2; ++mt) {
                unsigned a0, a1, a2, a3;
                ldmatrix_x4(a0, a1, a2, a3,
                            Abase + (unsigned)((mt * 16 * XROW + i * 64 + s4 * 16) * 2));
                mma16816(acc[mt][0][0], acc[mt][0][1], acc[mt][0][2], acc[mt][0][3],
                         a0, a1, a2, a3, b00, b01);
                mma16816(acc[mt][1][0], acc[mt][1][1], acc[mt][1][2], acc[mt][1][3],
                         a0, a1, a2, a3, b10, b11);
            }
        }

        // out += s*acc - s*(64+z)*X   (X = sum of fp16-rounded x -> 64 cancels)
        float Xv[4];
#pragma unroll
        for (int jj = 0; jj < 4; ++jj)
            Xv[jj] = sX[((lane >> 2) + 8 * jj) * 9 + i];
#pragma unroll
        for (int g = 0; g < 2; ++g) {
            const int nl = g ? nloc1 : nloc0;
            const float2 sv = *reinterpret_cast<const float2*>(&sS[i * NTILE + nl]);
            const float2 zv = *reinterpret_cast<const float2*>(&sZ[i * NTILE + nl]);
            const float s0 = sv.x, s1 = sv.y;
            const float u0 = s0 * (zv.x + 64.f);
            const float u1 = s1 * (zv.y + 64.f);
#pragma unroll
            for (int mt = 0; mt < 2; ++mt) {
                fin[mt][g][0] = fmaf(s0, acc[mt][g][0], fmaf(-u0, Xv[mt * 2 + 0], fin[mt][g][0]));
                fin[mt][g][1] = fmaf(s1, acc[mt][g][1], fmaf(-u1, Xv[mt * 2 + 0], fin[mt][g][1]));
                fin[mt][g][2] = fmaf(s0, acc[mt][g][2], fmaf(-u0, Xv[mt * 2 + 1], fin[mt][g][2]));
                fin[mt][g][3] = fmaf(s1, acc[mt][g][3], fmaf(-u1, Xv[mt * 2 + 1], fin[mt][g][3]));
            }
        }
    }

    // ---- epilogue: write partials (bias folded in on kb==0) ----
    float* part = &g_partial[kb][0];
#pragma unroll
    for (int g = 0; g < 2; ++g) {
        const int nS = n0 + (g ? nloc1 : nloc0);
        float2 bsv = make_float2(0.f, 0.f);
        if (kb == 0) bsv = *reinterpret_cast<const float2*>(bias + nS);
#pragma unroll
        for (int mp = 0; mp < 2; ++mp) {
#pragma unroll
            for (int cp = 0; cp < 2; ++cp) {
                int t = mp * 16 + (lane >> 2) + cp * 8;
                float2 o;
                o.x = fin[mp][g][cp * 2 + 0] + bsv.x;
                o.y = fin[mp][g][cp * 2 + 1] + bsv.y;
                *reinterpret_cast<float2*>(part + (size_t)t * NDIM + nS) = o;
            }
        }
    }
}

// ---------------- combine kernel ----------------
__global__ void awq_combine_kernel(float* __restrict__ out) {
    const int j = blockIdx.x * 256 + threadIdx.x;   // < 88064 float4s
    float4 r = reinterpret_cast<const float4*>(g_partial[0])[j];
#pragma unroll
    for (int s = 1; s < SPLITK; ++s) {
        float4 p = reinterpret_cast<const float4*>(g_partial[s])[j];
        r.x += p.x; r.y += p.y; r.z += p.z; r.w += p.w;
    }
    reinterpret_cast<float4*>(out)[j] = r;
}

// ---------------- launch ----------------
extern "C" void kernel_launch(void* const* d_in, const int* in_sizes, int n_in,
                              void* d_out, int out_size) {
    const float* x       = (const float*)d_in[0];
    const int*   qweight = (const int*)d_in[1];
    const float* wscales = (const float*)d_in[2];
    const float* wzeros  = (const float*)d_in[3];
    const float* bias    = (const float*)d_in[4];
    float* out = (float*)d_out;
    (void)in_sizes; (void)n_in; (void)out_size;

    awq_main_kernel<<<dim3(GRID_N, SPLITK), 256>>>(x, qweight, wscales, wzeros, bias);
    awq_combine_kernel<<<(TOK * NDIM) / (256 * 4), 256>>>(out);
}

// round 14
// speedup vs baseline: 1.5670x; 1.5670x over previous
#include <cuda_runtime.h>
#include <cuda_fp16.h>

// ---------------- problem constants ----------------
#define TOK      32
#define KDIM     4096
#define NDIM     11008
#define NTILE    128                 // output columns per CTA (16 per warp)
#define GRID_N   (NDIM / NTILE)      // 86
#define SPLITK   8
#define NCHUNK_G 64                  // total k-chunks of 64 (== group size)
#define CPC      (NCHUNK_G / SPLITK) // 8 chunks per CTA
#define KWORDS   2048                // int32 words per packed row
#define XROW     520                 // smem A row stride in halfs (1040B, cf-free)

// x in fp16, k PERMUTED within each 64-group to match the PRMT/LOP3 fragment
// packing: orig k (j = (k&63)>>1) ->
//   khat = 16*((j>>1)&3) + 2*(j>>3) + (j&1) + 8*(k&1)
__device__ __half g_xparts[TOK * KDIM];
// per-(token, group) sums of the fp16-ROUNDED x (fp32) -> +64 offset cancels
__device__ float  g_xsum[TOK * NCHUNK_G];

// ---------------- prep kernel (also zeroes out for the atomic epilogue) ----
__global__ void awq_prep_kernel(const float* __restrict__ x,
                                float* __restrict__ out) {
    const int blk = blockIdx.x;
    const int tid = threadIdx.x;
    const int t   = blk >> 3;
    const int k0  = (blk & 7) * 512 + tid * 2;     // even
    float2 v = *reinterpret_cast<const float2*>(x + (size_t)t * KDIM + k0);

    __half h0 = __float2half_rn(v.x), h1 = __float2half_rn(v.y);

    const int j    = (k0 & 63) >> 1;
    const int khat = 16 * ((j >> 1) & 3) + 2 * (j >> 3) + (j & 1);
    __half* xp = g_xparts + (size_t)t * KDIM + (k0 & ~63);
    xp[khat]     = h0;   // even k -> b0 slot
    xp[khat + 8] = h1;   // odd  k -> b1 slot

    float psum = __half2float(h0) + __half2float(h1);
#pragma unroll
    for (int d = 1; d < 32; d <<= 1)
        psum += __shfl_xor_sync(0xFFFFFFFFu, psum, d);
    if ((tid & 31) == 0) {
        int grp = (blk & 7) * 8 + (tid >> 5);
        g_xsum[t * NCHUNK_G + grp] = psum;
    }

    // zero the output (poisoned by harness; main accumulates atomically)
    const int jd = blk * 256 + tid;                 // 0..65535
    float4 zq = make_float4(0.f, 0.f, 0.f, 0.f);
    reinterpret_cast<float4*>(out)[jd] = zq;
    const int jd2 = jd + 65536;
    if (jd2 < (TOK * NDIM) / 4)
        reinterpret_cast<float4*>(out)[jd2] = zq;
}

// ---------------- helpers ----------------
static __device__ __forceinline__ unsigned smem_u32(const void* p) {
    unsigned a;
    asm("{ .reg .u64 t; cvta.to.shared.u64 t, %1; cvt.u32.u64 %0, t; }"
        : "=r"(a) : "l"(p));
    return a;
}
static __device__ __forceinline__ void ldmatrix_x4(unsigned& a0, unsigned& a1,
                                                   unsigned& a2, unsigned& a3,
                                                   unsigned addr) {
    asm volatile("ldmatrix.sync.aligned.m8n8.x4.shared.b16 {%0,%1,%2,%3}, [%4];"
                 : "=r"(a0), "=r"(a1), "=r"(a2), "=r"(a3) : "r"(addr));
}
static __device__ __forceinline__ void mma16816(float& d0, float& d1, float& d2, float& d3,
                                                unsigned a0, unsigned a1, unsigned a2, unsigned a3,
                                                unsigned b0, unsigned b1) {
    asm volatile("mma.sync.aligned.m16n8k16.row.col.f32.f16.f16.f32 "
                 "{%0,%1,%2,%3}, {%4,%5,%6,%7}, {%8,%9}, {%0,%1,%2,%3};"
                 : "+f"(d0), "+f"(d1), "+f"(d2), "+f"(d3)
                 : "r"(a0), "r"(a1), "r"(a2), "r"(a3), "r"(b0), "r"(b1));
}
static __device__ __forceinline__ unsigned prmt(unsigned a, unsigned b, unsigned s) {
    unsigned r;
    asm("prmt.b32 %0, %1, %2, %3;" : "=r"(r) : "r"(a), "r"(b), "r"(s));
    return r;
}
// (a & b) | c  -> immLut 0xEA ; yields fp16 {64+q} when b=0x00F000F0, c=0x54005400
static __device__ __forceinline__ unsigned lop3_ea(unsigned a, unsigned b, unsigned c) {
    unsigned r;
    asm("lop3.b32 %0, %1, %2, %3, 0xEA;" : "=r"(r) : "r"(a), "r"(b), "r"(c));
    return r;
}
#define NIB_MASK 0x00F000F0u
#define MAGIC64  0x54005400u

// ---------------- main kernel ----------------
__global__ void __launch_bounds__(256, 2)
awq_main_kernel(const int* __restrict__ qweight,
                const float* __restrict__ wscales,
                const float* __restrict__ wzeros,
                const float* __restrict__ bias,
                float* __restrict__ out) {
    __shared__ __align__(16) __half sA[32 * XROW];   // 33280 B
    __shared__ float sX[32 * 9];                      // 1152 B
    __shared__ float sS[CPC * NTILE];                 // 4096 B
    __shared__ float sZ[CPC * NTILE];                 // 4096 B

    const int tid  = threadIdx.x;
    const int wid  = tid >> 5;
    const int lane = tid & 31;
    const int n0   = blockIdx.x * NTILE;
    const int kb   = blockIdx.y;
    const int g0   = kb * CPC;

    // ---- B-side: warp owns 16 n = 2 groups of 8 ----
    const int npbase = (n0 >> 2) + wid * 4 + (lane >> 4);
    const int* qb0 = qweight + (size_t)npbase * KWORDS + g0 * 32 + 8 * (lane & 3);
    const int* qb1 = qb0 + 2 * KWORDS;

    // byte-gather selector: result byte0 = a.byte(bi), byte2 = b.byte(bi)
    const unsigned bi  = (unsigned)((lane >> 2) & 3);
    const unsigned sel = bi | ((4u + bi) << 8);

    // ---- accumulator-side n (per group) ----
    const int nloc0 = wid * 16 + 2 * (lane & 3);
    const int nloc1 = nloc0 + 8;

    // ---- s/z prologue: coalesced into smem ----
    {
        const int g = tid >> 5, nn = lane * 4;
        *reinterpret_cast<float4*>(&sS[g * NTILE + nn]) =
            *reinterpret_cast<const float4*>(wscales + (size_t)(g0 + g) * NDIM + n0 + nn);
        *reinterpret_cast<float4*>(&sZ[g * NTILE + nn]) =
            *reinterpret_cast<const float4*>(wzeros + (size_t)(g0 + g) * NDIM + n0 + nn);
    }

    // ---- one-shot A load: 32 rows x 512 halfs = 2048 uint4 ----
    {
        const int r = tid >> 3, pc = tid & 7;
        const uint4* src = reinterpret_cast<const uint4*>(
            g_xparts + (size_t)r * KDIM + g0 * 64) + pc;
        uint4* dst = reinterpret_cast<uint4*>(sA + r * XROW) + pc;
#pragma unroll
        for (int u = 0; u < 8; ++u) dst[u * 8] = src[u * 8];
    }
    // ---- X sums slice (stride 9 to dodge conflicts) ----
    sX[(tid >> 3) * 9 + (tid & 7)] = g_xsum[(tid >> 3) * NCHUNK_G + g0 + (tid & 7)];

    // ---- q prefetch ring, depth 2, 2 groups ----
    int4 qr[2][2][2];
#pragma unroll
    for (int j = 0; j < 2; ++j) {
        qr[j][0][0] = *reinterpret_cast<const int4*>(qb0 + j * 32);
        qr[j][0][1] = *reinterpret_cast<const int4*>(qb0 + j * 32 + 4);
        qr[j][1][0] = *reinterpret_cast<const int4*>(qb1 + j * 32);
        qr[j][1][1] = *reinterpret_cast<const int4*>(qb1 + j * 32 + 4);
    }
    __syncthreads();

    // fin[mt][ng][4]
    float fin[2][2][4];
#pragma unroll
    for (int m = 0; m < 2; ++m)
#pragma unroll
        for (int g = 0; g < 2; ++g)
#pragma unroll
            for (int c = 0; c < 4; ++c) fin[m][g][c] = 0.f;

    const unsigned Abase = smem_u32(sA)
        + (unsigned)(((lane & 15) * XROW + (lane >> 4) * 8) * 2);

#pragma unroll
    for (int i = 0; i < CPC; ++i) {
        const int slot = i & 1;
        const int4 qg0a = qr[slot][0][0], qg0b = qr[slot][0][1];
        const int4 qg1a = qr[slot][1][0], qg1b = qr[slot][1][1];
        if (i + 2 < CPC) {
            qr[slot][0][0] = *reinterpret_cast<const int4*>(qb0 + (i + 2) * 32);
            qr[slot][0][1] = *reinterpret_cast<const int4*>(qb0 + (i + 2) * 32 + 4);
            qr[slot][1][0] = *reinterpret_cast<const int4*>(qb1 + (i + 2) * 32);
            qr[slot][1][1] = *reinterpret_cast<const int4*>(qb1 + (i + 2) * 32 + 4);
        }

        float acc[2][2][4];
#pragma unroll
        for (int m = 0; m < 2; ++m)
#pragma unroll
            for (int g = 0; g < 2; ++g)
#pragma unroll
                for (int c = 0; c < 4; ++c) acc[m][g][c] = 0.f;

        const int qa0[8] = { qg0a.x, qg0a.y, qg0a.z, qg0a.w,
                             qg0b.x, qg0b.y, qg0b.z, qg0b.w };
        const int qa1[8] = { qg1a.x, qg1a.y, qg1a.z, qg1a.w,
                             qg1b.x, qg1b.y, qg1b.z, qg1b.w };
#pragma unroll
        for (int s4 = 0; s4 < 4; ++s4) {
            // PRMT gathers this thread's n-byte from both k-words;
            // LOP3 injects nibbles into fp16 {64+q} (hi nibble at mantissa[7:4])
            const unsigned p0  = prmt((unsigned)qa0[2 * s4], (unsigned)qa0[2 * s4 + 1], sel);
            const unsigned b01 = lop3_ea(p0,      NIB_MASK, MAGIC64);   // odd k  -> b1
            const unsigned b00 = lop3_ea(p0 << 4, NIB_MASK, MAGIC64);   // even k -> b0
            const unsigned p1  = prmt((unsigned)qa1[2 * s4], (unsigned)qa1[2 * s4 + 1], sel);
            const unsigned b11 = lop3_ea(p1,      NIB_MASK, MAGIC64);
            const unsigned b10 = lop3_ea(p1 << 4, NIB_MASK, MAGIC64);
#pragma unroll
            for (int mt = 0; mt < 2; ++mt) {
                unsigned a0, a1, a2, a3;
                ldmatrix_x4(a0, a1, a2, a3,
                            Abase + (unsigned)((mt * 16 * XROW + i * 64 + s4 * 16) * 2));
                mma16816(acc[mt][0][0], acc[mt][0][1], acc[mt][0][2], acc[mt][0][3],
                         a0, a1, a2, a3, b00, b01);
                mma16816(acc[mt][1][0], acc[mt][1][1], acc[mt][1][2], acc[mt][1][3],
                         a0, a1, a2, a3, b10, b11);
            }
        }

        // out += s*acc - s*(64+z)*X   (X = sum of fp16-rounded x -> 64 cancels)
        float Xv[4];
#pragma unroll
        for (int jj = 0; jj < 4; ++jj)
            Xv[jj] = sX[((lane >> 2) + 8 * jj) * 9 + i];
#pragma unroll
        for (int g = 0; g < 2; ++g) {
            const int nl = g ? nloc1 : nloc0;
            const float2 sv = *reinterpret_cast<const float2*>(&sS[i * NTILE + nl]);
            const float2 zv = *reinterpret_cast<const float2*>(&sZ[i * NTILE + nl]);
            const float s0 = sv.x, s1 = sv.y;
            const float u0 = s0 * (zv.x + 64.f);
            const float u1 = s1 * (zv.y + 64.f);
#pragma unroll
            for (int mt = 0; mt < 2; ++mt) {
                fin[mt][g][0] = fmaf(s0, acc[mt][g][0], fmaf(-u0, Xv[mt * 2 + 0], fin[mt][g][0]));
                fin[mt][g][1] = fmaf(s1, acc[mt][g][1], fmaf(-u1, Xv[mt * 2 + 0], fin[mt][g][1]));
                fin[mt][g][2] = fmaf(s0, acc[mt][g][2], fmaf(-u0, Xv[mt * 2 + 1], fin[mt][g][2]));
                fin[mt][g][3] = fmaf(s1, acc[mt][g][3], fmaf(-u1, Xv[mt * 2 + 1], fin[mt][g][3]));
            }
        }
    }

    // ---- epilogue: atomic-accumulate into out (bias folded in on kb==0) ----
#pragma unroll
    for (int g = 0; g < 2; ++g) {
        const int nS = n0 + (g ? nloc1 : nloc0);
        float2 bsv = make_float2(0.f, 0.f);
        if (kb == 0) bsv = *reinterpret_cast<const float2*>(bias + nS);
#pragma unroll
        for (int mp = 0; mp < 2; ++mp) {
#pragma unroll
            for (int cp = 0; cp < 2; ++cp) {
                int t = mp * 16 + (lane >> 2) + cp * 8;
                float* op = out + (size_t)t * NDIM + nS;
                atomicAdd(op,     fin[mp][g][cp * 2 + 0] + bsv.x);
                atomicAdd(op + 1, fin[mp][g][cp * 2 + 1] + bsv.y);
            }
        }
    }
}

// ---------------- launch ----------------
extern "C" void kernel_launch(void* const* d_in, const int* in_sizes, int n_in,
                              void* d_out, int out_size) {
    const float* x       = (const float*)d_in[0];
    const int*   qweight = (const int*)d_in[1];
    const float* wscales = (const float*)d_in[2];
    const float* wzeros  = (const float*)d_in[3];
    const float* bias    = (const float*)d_in[4];
    float* out = (float*)d_out;
    (void)in_sizes; (void)n_in; (void)out_size;

    awq_prep_kernel<<<TOK * 8, 256>>>(x, out);
    awq_main_kernel<<<dim3(GRID_N, SPLITK), 256>>>(qweight, wscales, wzeros, bias, out);
}